// round 12
// baseline (speedup 1.0000x reference)
#include <cuda_runtime.h>
#include <math.h>
#include <stdint.h>

// Problem constants
#define BATCH   32
#define NNODE   128
#define NIN     64
#define NHID    128
#define NOUT    64
#define NEDGE   16256            // N*(N-1)
#define M_ROWS  4096             // BATCH*NNODE
#define NBLK    128              // M_ROWS / BM (BM=32)

// ---------------- scratch (device globals; no allocation allowed) -----------
__device__ __align__(16) float g_h2[M_ROWS * NHID];   // raw h2 (pre-BN-scale)
__device__ __align__(16) float g_w1t[NIN * NHID];     // [k=64][n=128]
__device__ __align__(16) float g_w2t[NHID * NHID];    // [k][n]
__device__ __align__(16) float g_woutt[NHID * NHID];  // [h][oc] oc<64: sender, oc>=64: recv
__device__ __align__(16) float g_bias[NHID];          // first 64 = folded bias, rest 0
__device__ __align__(16) float g_sa[NHID];            // BN scale per channel
__device__ __align__(16) float g_psum[NBLK * NHID];
__device__ __align__(16) float g_psq [NBLK * NHID];
__device__ unsigned g_c0;        // phase-0 (transpose) arrivals
__device__ unsigned g_c1;        // mlp-stats arrivals

__device__ __forceinline__ float elu(float x) { return x > 0.f ? x : expm1f(x); }

// ---------------- K1: prep + MLP + BN (BM=32, 128 blocks x 256 thr) ---------
__global__ __launch_bounds__(256) void mlp_kernel(
    const float* __restrict__ X,     // [4096][64]
    const float* __restrict__ W1,    // [128][64]
    const float* __restrict__ b1v,
    const float* __restrict__ W2,    // [128][128]
    const float* __restrict__ b2v,
    const float* __restrict__ gamma,
    const float* __restrict__ beta,
    const float* __restrict__ Wout,  // [64][256]
    const float* __restrict__ bout,
    float* __restrict__ H2,          // [4096][128]
    float* __restrict__ psum,
    float* __restrict__ psq)
{
    __shared__ float Bs[32][128];    // 16KB weight k-tile (last blk tail: scf)
    __shared__ float h1s[32][128];   // 16KB h1
    __shared__ float S[2048];        // 8KB X-tile / rsum+rsq / ssum+ssq
    __shared__ unsigned s_done;

    const int tid = threadIdx.x;
    const int tx  = tid & 31;
    const int ty  = tid >> 5;        // 0..7, 4 rows each
    const int row0 = blockIdx.x * 32;

    // ---- Phase 0: X tile + cooperative weight transposes ----
    #pragma unroll
    for (int i = 0; i < 2; i++) {
        int f = tid + i * 256;
        int m = f >> 4, kg = f & 15;
        *(float4*)&S[m * 64 + kg * 4] = *(const float4*)&X[(row0 + m) * 64 + kg * 4];
    }
    {
        int t0 = blockIdx.x * 256 + tid;
        #pragma unroll
        for (int rep = 0; rep < 2; rep++) {
            int i = t0 + rep * 32768;
            if (i < 8192) {
                int f = i >> 7, h = i & 127;
                g_w1t[i] = W1[h * NIN + f];
            } else if (i < 24576) {
                int j = i - 8192;
                int k = j >> 7, n = j & 127;
                g_w2t[j] = W2[n * NHID + k];
            } else if (i < 40960) {
                int j = i - 24576;
                int h = j >> 7, oc = j & 127;
                g_woutt[j] = Wout[(oc & 63) * 256 + (oc >> 6) * 128 + h];
            }
        }
    }
    __threadfence();
    __syncthreads();
    if (tid == 0) {
        atomicAdd(&g_c0, 1u);
        while (atomicAdd(&g_c0, 0u) < (unsigned)NBLK) __nanosleep(64);
        __threadfence();
    }
    __syncthreads();

    // ---- Phase 1: h1 = ELU(X @ W1t + b1) ----
    float acc[4][4] = {};
    for (int kb = 0; kb < NIN; kb += 32) {
        __syncthreads();
        #pragma unroll
        for (int i = 0; i < 4; i++) {
            int f = tid + i * 256;
            int k = f >> 5, ng = f & 31;
            *(float4*)&Bs[k][ng * 4] = *(const float4*)&g_w1t[(kb + k) * 128 + ng * 4];
        }
        __syncthreads();
        #pragma unroll
        for (int k = 0; k < 32; k++) {
            float4 b4 = *(float4*)&Bs[k][tx * 4];
            #pragma unroll
            for (int i = 0; i < 4; i++) {
                float a = S[(ty * 4 + i) * 64 + kb + k];
                acc[i][0] += a * b4.x;
                acc[i][1] += a * b4.y;
                acc[i][2] += a * b4.z;
                acc[i][3] += a * b4.w;
            }
        }
    }
    {
        float4 bb = *(const float4*)&b1v[tx * 4];
        #pragma unroll
        for (int i = 0; i < 4; i++) {
            float4 o;
            o.x = elu(acc[i][0] + bb.x);
            o.y = elu(acc[i][1] + bb.y);
            o.z = elu(acc[i][2] + bb.z);
            o.w = elu(acc[i][3] + bb.w);
            *(float4*)&h1s[ty * 4 + i][tx * 4] = o;
        }
    }

    // ---- Phase 2: h2 = ELU(h1 @ W2t + b2) -> global + stats ----
    float acc2[4][4] = {};
    for (int kb = 0; kb < NHID; kb += 32) {
        __syncthreads();
        #pragma unroll
        for (int i = 0; i < 4; i++) {
            int f = tid + i * 256;
            int k = f >> 5, ng = f & 31;
            *(float4*)&Bs[k][ng * 4] = *(const float4*)&g_w2t[(kb + k) * 128 + ng * 4];
        }
        __syncthreads();
        #pragma unroll
        for (int k = 0; k < 32; k++) {
            float4 b4 = *(float4*)&Bs[k][tx * 4];
            #pragma unroll
            for (int i = 0; i < 4; i++) {
                float a = h1s[ty * 4 + i][kb + k];
                acc2[i][0] += a * b4.x;
                acc2[i][1] += a * b4.y;
                acc2[i][2] += a * b4.z;
                acc2[i][3] += a * b4.w;
            }
        }
    }

    float s[4]  = {0.f, 0.f, 0.f, 0.f};
    float s2[4] = {0.f, 0.f, 0.f, 0.f};
    {
        float4 bb = *(const float4*)&b2v[tx * 4];
        #pragma unroll
        for (int i = 0; i < 4; i++) {
            float4 o;
            o.x = elu(acc2[i][0] + bb.x);
            o.y = elu(acc2[i][1] + bb.y);
            o.z = elu(acc2[i][2] + bb.z);
            o.w = elu(acc2[i][3] + bb.w);
            s[0] += o.x; s2[0] += o.x * o.x;
            s[1] += o.y; s2[1] += o.y * o.y;
            s[2] += o.z; s2[2] += o.z * o.z;
            s[3] += o.w; s2[3] += o.w * o.w;
            *(float4*)&H2[(row0 + ty * 4 + i) * 128 + tx * 4] = o;
        }
    }
    __syncthreads();   // S dead; reuse as rsum/rsq
    #pragma unroll
    for (int j = 0; j < 4; j++) {
        S[ty * 128 + tx * 4 + j]        = s[j];
        S[1024 + ty * 128 + tx * 4 + j] = s2[j];
    }
    __syncthreads();
    if (tid < 128) {
        float ps = 0.f, pq = 0.f;
        #pragma unroll
        for (int g = 0; g < 8; g++) {
            ps += S[g * 128 + tid];
            pq += S[1024 + g * 128 + tid];
        }
        psum[blockIdx.x * NHID + tid] = ps;
        psq [blockIdx.x * NHID + tid] = pq;
    }
    __threadfence();
    __syncthreads();
    if (tid == 0) {
        __threadfence();
        s_done = atomicAdd(&g_c1, 1u);
    }
    __syncthreads();
    if (s_done != NBLK - 1) return;     // non-last blocks exit

    // ---- LAST BLOCK: global stats + BN fold scalars + folded bias ----
    float* ssum = S;
    float* ssq  = S + 1024;
    float* scf  = (float*)Bs;
    __syncthreads();
    {
        const int c4  = tid & 31;
        const int grp = tid >> 5;
        float4 A1 = make_float4(0.f, 0.f, 0.f, 0.f);
        float4 A2 = make_float4(0.f, 0.f, 0.f, 0.f);
        #pragma unroll
        for (int i = 0; i < 16; i++) {
            int blk = grp * 16 + i;
            float4 p = *(const float4*)&psum[blk * 128 + c4 * 4];
            float4 q = *(const float4*)&psq [blk * 128 + c4 * 4];
            A1.x += p.x; A1.y += p.y; A1.z += p.z; A1.w += p.w;
            A2.x += q.x; A2.y += q.y; A2.z += q.z; A2.w += q.w;
        }
        __syncthreads();
        *(float4*)&ssum[grp * 128 + c4 * 4] = A1;
        *(float4*)&ssq [grp * 128 + c4 * 4] = A2;
    }
    __syncthreads();
    if (tid < 128) {
        float ts = 0.f, tq = 0.f;
        #pragma unroll
        for (int g = 0; g < 8; g++) { ts += ssum[g * 128 + tid]; tq += ssq[g * 128 + tid]; }
        const float inv = 1.f / (float)M_ROWS;
        float mean = ts * inv;
        float var  = tq * inv - mean * mean;
        float a = gamma[tid] * rsqrtf(var + 1e-5f);
        float c = beta[tid] - a * mean;
        g_sa[tid] = a;
        scf[tid]  = c;
    }
    __syncthreads();
    {
        const int o  = tid >> 2;
        const int l4 = tid & 3;
        float bs = 0.f;
        #pragma unroll
        for (int i = 0; i < 16; i++) {
            float4 w = *(const float4*)&Wout[o * 256 + l4 * 64 + i * 4];
            int j0 = (l4 & 1) * 64 + i * 4;
            bs += w.x * scf[j0] + w.y * scf[j0 + 1] + w.z * scf[j0 + 2] + w.w * scf[j0 + 3];
        }
        bs += __shfl_down_sync(0xffffffffu, bs, 2, 4);
        bs += __shfl_down_sync(0xffffffffu, bs, 1, 4);
        if (l4 == 0) g_bias[o] = bs + bout[o];
    }
}

// ---------------- K2: edge kernel = per-block gemm3 + edge writes -----------
// Block (b, r0): computes ys = (h2[b]*sa) @ woutt[:,0:64] + bias  (128x64)
// and yr = (h2[b,r0:r0+16]*sa) @ woutt[:,64:128] (16x64) in smem, then streams
// its 0.5MB of edges. gemm overlaps co-resident blocks' store phases.
// Edge e: recv = e/127, i = e%127, send = i + (i >= recv).
__global__ __launch_bounds__(256) void edge_gemm_kernel(
    const float* __restrict__ H2, float* __restrict__ out)
{
    __shared__ float U[8320];            // As[128*33] + Bs[32*128]; later ys[128*64]
    __shared__ float yr_sh[16 * 64];
    __shared__ float sa_sh[128];
    __shared__ float bias_sh[64];

    float* AsP = U;                      // stride 33 (bank-conflict-free bcast)
    float* BsP = U + 4224;
    float* ysP = U;                      // stride 64, valid after gemm

    const int tid = threadIdx.x;
    if (blockIdx.x == 0 && tid == 0) {   // reset K1 sync state for next replay
        g_c0 = 0u; g_c1 = 0u;
    }
    const int b    = blockIdx.x >> 3;
    const int r0   = (blockIdx.x & 7) * 16;
    const int rowb = b << 7;

    if (tid < 128) sa_sh[tid] = g_sa[tid];
    if (tid < 64)  bias_sh[tid] = g_bias[tid];

    const int colg = tid & 15;           // ys cols colg*4
    const int rowg = tid >> 4;           // ys rows rowg*8 .. +7 ; yr row r0+rowg

    float acc[8][4] = {};
    float accr[4] = {0.f, 0.f, 0.f, 0.f};

    for (int kb = 0; kb < NHID; kb += 32) {
        __syncthreads();
        // As: 128 rows x 32 k, sa-scaled; 1024 float4 / 256 thr
        #pragma unroll
        for (int i = 0; i < 4; i++) {
            int f = tid + i * 256;
            int r = f >> 3, kg = f & 7;
            float4 v  = *(const float4*)&H2[(rowb + r) * 128 + kb + kg * 4];
            float4 sc = *(const float4*)&sa_sh[kb + kg * 4];
            AsP[r * 33 + kg * 4 + 0] = v.x * sc.x;
            AsP[r * 33 + kg * 4 + 1] = v.y * sc.y;
            AsP[r * 33 + kg * 4 + 2] = v.z * sc.z;
            AsP[r * 33 + kg * 4 + 3] = v.w * sc.w;
        }
        // Bs: 32 k x 128 oc
        #pragma unroll
        for (int i = 0; i < 4; i++) {
            int f = tid + i * 256;
            int k = f >> 5, ng = f & 31;
            *(float4*)&BsP[k * 128 + ng * 4] = *(const float4*)&g_woutt[(kb + k) * 128 + ng * 4];
        }
        __syncthreads();
        #pragma unroll
        for (int k = 0; k < 32; k++) {
            float4 b4 = *(float4*)&BsP[k * 128 + colg * 4];
            float4 br = *(float4*)&BsP[k * 128 + 64 + colg * 4];
            float  ar = AsP[(r0 + rowg) * 33 + k];
            accr[0] += ar * br.x;
            accr[1] += ar * br.y;
            accr[2] += ar * br.z;
            accr[3] += ar * br.w;
            #pragma unroll
            for (int i = 0; i < 8; i++) {
                float a = AsP[(rowg * 8 + i) * 33 + k];
                acc[i][0] += a * b4.x;
                acc[i][1] += a * b4.y;
                acc[i][2] += a * b4.z;
                acc[i][3] += a * b4.w;
            }
        }
    }
    __syncthreads();     // As/Bs dead; U becomes ys

    {
        float4 bb = *(const float4*)&bias_sh[colg * 4];
        #pragma unroll
        for (int i = 0; i < 8; i++) {
            float4 o;
            o.x = acc[i][0] + bb.x;
            o.y = acc[i][1] + bb.y;
            o.z = acc[i][2] + bb.z;
            o.w = acc[i][3] + bb.w;
            *(float4*)&ysP[(rowg * 8 + i) * 64 + colg * 4] = o;
        }
        float4 r4;
        r4.x = accr[0]; r4.y = accr[1]; r4.z = accr[2]; r4.w = accr[3];
        *(float4*)&yr_sh[rowg * 64 + colg * 4] = r4;   // yr has zero bias
    }
    __syncthreads();

    // ---- write edges: q chunk x 8 senders per thread, 16 receivers ----
    const int q  = tid & 15;
    const int sg = tid >> 4;             // senders sg*8 .. +7
    float4* outv = (float4*)out;
    const long base_b = (long)b * NEDGE;

    #pragma unroll 1
    for (int rl = 0; rl < 16; rl++) {
        const int rg = r0 + rl;
        float4 yr4 = *(float4*)&yr_sh[rl * 64 + q * 4];
        const long base = (base_b + (long)rg * 127) * 16 + q;
        #pragma unroll
        for (int j = 0; j < 8; j++) {
            int s = sg * 8 + j;
            if (s == rg) continue;       // no self-loop
            int i = s - (s > rg);
            float4 a = *(const float4*)&ysP[s * 64 + q * 4];
            float4 o;
            o.x = a.x + yr4.x;
            o.y = a.y + yr4.y;
            o.z = a.z + yr4.z;
            o.w = a.w + yr4.w;
            __stcs(&outv[base + (long)i * 16], o);
        }
    }
}

// ---------------- launcher ---------------------------------------------------
extern "C" void kernel_launch(void* const* d_in, const int* in_sizes, int n_in,
                              void* d_out, int out_size) {
    const float* x       = (const float*)d_in[0];
    const float* W1      = (const float*)d_in[3];
    const float* b1      = (const float*)d_in[4];
    const float* W2      = (const float*)d_in[5];
    const float* b2      = (const float*)d_in[6];
    const float* gamma   = (const float*)d_in[7];
    const float* beta    = (const float*)d_in[8];
    const float* Wout    = (const float*)d_in[9];
    const float* bout    = (const float*)d_in[10];
    float* out = (float*)d_out;

    float *p_h2, *p_psum, *p_psq;
    cudaGetSymbolAddress((void**)&p_h2,   g_h2);
    cudaGetSymbolAddress((void**)&p_psum, g_psum);
    cudaGetSymbolAddress((void**)&p_psq,  g_psq);

    // prep + MLP + BN (last block folds scalars + bias)
    mlp_kernel<<<NBLK, 256>>>(x, W1, b1, W2, b2, gamma, beta, Wout, bout,
                              p_h2, p_psum, p_psq);

    // per-block gemm3 + edge writes (gemm hides under the store wall)
    edge_gemm_kernel<<<256, 256>>>(p_h2, out);
}

// round 13
// speedup vs baseline: 1.1448x; 1.1448x over previous
#include <cuda_runtime.h>
#include <math.h>
#include <stdint.h>

// Problem constants
#define BATCH   32
#define NNODE   128
#define NIN     64
#define NHID    128
#define NOUT    64
#define NEDGE   16256            // N*(N-1)
#define M_ROWS  4096             // BATCH*NNODE
#define NBLK    128              // M_ROWS / BM (BM=32)

// ---------------- scratch (device globals; no allocation allowed) -----------
__device__ __align__(16) float g_h2[M_ROWS * NHID];
__device__ __align__(16) float g_y [M_ROWS * NHID];   // cols 0..63 ys(+bias), 64..127 yr
__device__ __align__(16) float g_w1t[NIN * NHID];     // [k=64][n=128]
__device__ __align__(16) float g_w2t[NHID * NHID];    // [k][n]
__device__ __align__(16) float g_woutt[NHID * NHID];  // [h][oc] oc<64: sender, oc>=64: recv
__device__ __align__(16) float g_bias[NHID];          // first 64 = folded bias, rest 0
__device__ __align__(16) float g_sa[NHID];            // BN scale per channel
__device__ __align__(16) float g_psum[NBLK * NHID];
__device__ __align__(16) float g_psq [NBLK * NHID];
__device__ unsigned g_ctr;

__device__ __forceinline__ float elu(float x) { return x > 0.f ? x : expm1f(x); }

__device__ __forceinline__ void cp16(void* dst, const void* src) {
    uint32_t d = (uint32_t)__cvta_generic_to_shared(dst);
    asm volatile("cp.async.cg.shared.global [%0], [%1], 16;" :: "r"(d), "l"(src) : "memory");
}
#define CP_COMMIT()  asm volatile("cp.async.commit_group;" ::: "memory")
#define CP_WAIT(n)   asm volatile("cp.async.wait_group %0;" :: "n"(n) : "memory")

// ---------------- K0: prep (weight transposes + ctr reset) ------------------
__global__ void prep_kernel(const float* __restrict__ W1,
                            const float* __restrict__ W2,
                            const float* __restrict__ Wout) {
    int t = blockIdx.x * blockDim.x + threadIdx.x;
    if (t == 0) g_ctr = 0u;
    if (t < 8192) {
        int f = t >> 7, h = t & 127;
        g_w1t[t] = W1[h * NIN + f];
    } else if (t < 24576) {
        int i = t - 8192;
        int k = i >> 7, n = i & 127;
        g_w2t[i] = W2[n * NHID + k];
    } else if (t < 40960) {
        int i = t - 24576;
        int h = i >> 7, oc = i & 127;
        g_woutt[i] = Wout[(oc & 63) * 256 + (oc >> 6) * 128 + h];
    }
}

// ---------------- K1: fused MLP, resident weights, syncless k-loops ---------
// dyn smem: W1s[64*128] | W2s[128*128] | h1s[32*128] | S[2048]  = 122880 B
__global__ __launch_bounds__(256) void mlp_fused_kernel(
    const float* __restrict__ X,     // [4096][64]
    const float* __restrict__ b1v,
    const float* __restrict__ b2v,
    const float* __restrict__ gamma,
    const float* __restrict__ beta,
    const float* __restrict__ Wout,
    const float* __restrict__ bout,
    float* __restrict__ H2,          // [4096][128]
    float* __restrict__ psum,
    float* __restrict__ psq)
{
    extern __shared__ float smem[];
    float* W1s = smem;               // 8192 floats
    float* W2s = smem + 8192;        // 16384 floats
    float* h1s = smem + 24576;       // 4096 floats
    float* S   = smem + 28672;       // 2048 floats (X tile / stats)
    __shared__ unsigned s_done;

    const int tid = threadIdx.x;
    const int tx  = tid & 31;
    const int ty  = tid >> 5;        // 0..7, 4 rows each
    const int row0 = blockIdx.x * 32;

    // Prefetch whole weights: W1s (group old), then W2s (group young)
    #pragma unroll
    for (int i = 0; i < 8; i++) {
        int f = tid + i * 256;       // float4 index < 2048
        cp16(&W1s[f * 4], &g_w1t[f * 4]);
    }
    CP_COMMIT();
    #pragma unroll
    for (int i = 0; i < 16; i++) {
        int f = tid + i * 256;       // < 4096
        cp16(&W2s[f * 4], &g_w2t[f * 4]);
    }
    CP_COMMIT();

    // X tile (regular loads): 512 float4, 2 per thread
    #pragma unroll
    for (int i = 0; i < 2; i++) {
        int f = tid + i * 256;
        int m = f >> 4, kg = f & 15;
        *(float4*)&S[m * 64 + kg * 4] = *(const float4*)&X[(row0 + m) * 64 + kg * 4];
    }

    CP_WAIT(1);                      // W1s resident (W2s may still fly)
    __syncthreads();

    // ---- GEMM1: straight k-loop, no syncs ----
    float acc[4][4] = {};
    #pragma unroll 8
    for (int k = 0; k < NIN; k++) {
        float4 b4 = *(float4*)&W1s[k * 128 + tx * 4];
        #pragma unroll
        for (int i = 0; i < 4; i++) {
            float a = S[(ty * 4 + i) * 64 + k];
            acc[i][0] += a * b4.x;
            acc[i][1] += a * b4.y;
            acc[i][2] += a * b4.z;
            acc[i][3] += a * b4.w;
        }
    }
    {
        float4 bb = *(const float4*)&b1v[tx * 4];
        #pragma unroll
        for (int i = 0; i < 4; i++) {
            float4 o;
            o.x = elu(acc[i][0] + bb.x);
            o.y = elu(acc[i][1] + bb.y);
            o.z = elu(acc[i][2] + bb.z);
            o.w = elu(acc[i][3] + bb.w);
            *(float4*)&h1s[(ty * 4 + i) * 128 + tx * 4] = o;
        }
    }
    CP_WAIT(0);                      // W2s resident
    __syncthreads();                 // h1s visible

    // ---- GEMM2: straight k-loop, no syncs ----
    float acc2[4][4] = {};
    #pragma unroll 8
    for (int k = 0; k < NHID; k++) {
        float4 b4 = *(float4*)&W2s[k * 128 + tx * 4];
        #pragma unroll
        for (int i = 0; i < 4; i++) {
            float a = h1s[(ty * 4 + i) * 128 + k];
            acc2[i][0] += a * b4.x;
            acc2[i][1] += a * b4.y;
            acc2[i][2] += a * b4.z;
            acc2[i][3] += a * b4.w;
        }
    }

    // Epilogue: ELU + bias + per-block channel stats + store h2
    float s[4]  = {0.f, 0.f, 0.f, 0.f};
    float s2[4] = {0.f, 0.f, 0.f, 0.f};
    {
        float4 bb = *(const float4*)&b2v[tx * 4];
        #pragma unroll
        for (int i = 0; i < 4; i++) {
            float4 o;
            o.x = elu(acc2[i][0] + bb.x);
            o.y = elu(acc2[i][1] + bb.y);
            o.z = elu(acc2[i][2] + bb.z);
            o.w = elu(acc2[i][3] + bb.w);
            s[0] += o.x; s2[0] += o.x * o.x;
            s[1] += o.y; s2[1] += o.y * o.y;
            s[2] += o.z; s2[2] += o.z * o.z;
            s[3] += o.w; s2[3] += o.w * o.w;
            *(float4*)&H2[(row0 + ty * 4 + i) * 128 + tx * 4] = o;
        }
    }
    __syncthreads();   // S (X tile) dead; reuse as rsum/rsq
    #pragma unroll
    for (int j = 0; j < 4; j++) {
        S[ty * 128 + tx * 4 + j]        = s[j];
        S[1024 + ty * 128 + tx * 4 + j] = s2[j];
    }
    __syncthreads();
    if (tid < 128) {
        float ps = 0.f, pq = 0.f;
        #pragma unroll
        for (int g = 0; g < 8; g++) {
            ps += S[g * 128 + tid];
            pq += S[1024 + g * 128 + tid];
        }
        psum[blockIdx.x * NHID + tid] = ps;
        psq [blockIdx.x * NHID + tid] = pq;
    }
    __threadfence();
    __syncthreads();
    if (tid == 0) {
        __threadfence();
        s_done = atomicAdd(&g_ctr, 1u);
    }
    __syncthreads();
    if (s_done != NBLK - 1) return;

    // ---- LAST BLOCK ONLY: global stats + BN fold scalars + folded bias ----
    float* ssum = S;                 // [8][128]
    float* ssq  = S + 1024;          // [8][128]
    float* scf  = W1s;               // [128]
    __syncthreads();
    {
        const int c4  = tid & 31;    // 4 channels
        const int grp = tid >> 5;    // 16 blocks each
        float4 A1 = make_float4(0.f, 0.f, 0.f, 0.f);
        float4 A2 = make_float4(0.f, 0.f, 0.f, 0.f);
        #pragma unroll
        for (int i = 0; i < 16; i++) {
            int blk = grp * 16 + i;
            float4 p = *(const float4*)&psum[blk * 128 + c4 * 4];
            float4 q = *(const float4*)&psq [blk * 128 + c4 * 4];
            A1.x += p.x; A1.y += p.y; A1.z += p.z; A1.w += p.w;
            A2.x += q.x; A2.y += q.y; A2.z += q.z; A2.w += q.w;
        }
        __syncthreads();
        *(float4*)&ssum[grp * 128 + c4 * 4] = A1;
        *(float4*)&ssq [grp * 128 + c4 * 4] = A2;
    }
    __syncthreads();
    if (tid < 128) {
        float ts = 0.f, tq = 0.f;
        #pragma unroll
        for (int g = 0; g < 8; g++) { ts += ssum[g * 128 + tid]; tq += ssq[g * 128 + tid]; }
        const float inv = 1.f / (float)M_ROWS;
        float mean = ts * inv;
        float var  = tq * inv - mean * mean;
        float a = gamma[tid] * rsqrtf(var + 1e-5f);
        float c = beta[tid] - a * mean;
        g_sa[tid] = a;
        scf[tid]  = c;
    }
    __syncthreads();
    {
        const int o  = tid >> 2;
        const int l4 = tid & 3;
        float bs = 0.f;
        #pragma unroll
        for (int i = 0; i < 16; i++) {
            float4 w = *(const float4*)&Wout[o * 256 + l4 * 64 + i * 4];
            int j0 = (l4 & 1) * 64 + i * 4;
            bs += w.x * scf[j0] + w.y * scf[j0 + 1] + w.z * scf[j0 + 2] + w.w * scf[j0 + 3];
        }
        bs += __shfl_down_sync(0xffffffffu, bs, 2, 4);
        bs += __shfl_down_sync(0xffffffffu, bs, 1, 4);
        if (l4 == 0) g_bias[o] = bs + bout[o];
        if (tid >= 64 && tid < 128) g_bias[tid] = 0.f;
    }
}

// ---------------- K2: GEMM3 y = h2 @ (sa*Wout)T + bias, resident B ----------
// dyn smem: Ws[128*128] | As[32*128]  = 81920 B
__global__ __launch_bounds__(256) void gemm3_kernel(const float* __restrict__ A,
                                                    float* __restrict__ C) {
    extern __shared__ float smem[];
    float* Ws = smem;                // 16384 floats
    float* As = smem + 16384;        // 4096 floats
    __shared__ float sa_sh[128];
    __shared__ float bias_sh[128];

    const int tid = threadIdx.x;
    const int tx  = tid & 31;
    const int ty  = tid >> 5;
    const int row0 = blockIdx.x * 32;

    #pragma unroll
    for (int i = 0; i < 16; i++) {
        int f = tid + i * 256;       // < 4096 float4
        cp16(&Ws[f * 4], &g_woutt[f * 4]);
    }
    #pragma unroll
    for (int i = 0; i < 4; i++) {
        int f = tid + i * 256;       // < 1024 float4
        cp16(&As[f * 4], &A[row0 * 128 + f * 4]);
    }
    CP_COMMIT();
    if (tid < 128) { sa_sh[tid] = g_sa[tid]; bias_sh[tid] = g_bias[tid]; }
    CP_WAIT(0);
    __syncthreads();

    // fold sa into B rows once: Ws[k][oc] *= sa[k]
    #pragma unroll
    for (int i = 0; i < 16; i++) {
        int f = tid + i * 256;       // float4 index < 4096
        int k = f >> 5;
        float4 v = *(float4*)&Ws[f * 4];
        float sc = sa_sh[k];
        v.x *= sc; v.y *= sc; v.z *= sc; v.w *= sc;
        *(float4*)&Ws[f * 4] = v;
    }
    __syncthreads();

    float acc[4][4] = {};
    #pragma unroll 8
    for (int k = 0; k < NHID; k++) {
        float4 b4 = *(float4*)&Ws[k * 128 + tx * 4];
        #pragma unroll
        for (int i = 0; i < 4; i++) {
            float a = As[(ty * 4 + i) * 128 + k];
            acc[i][0] += a * b4.x;
            acc[i][1] += a * b4.y;
            acc[i][2] += a * b4.z;
            acc[i][3] += a * b4.w;
        }
    }

    float4 bb = *(const float4*)&bias_sh[tx * 4];
    #pragma unroll
    for (int i = 0; i < 4; i++) {
        float4 o;
        o.x = acc[i][0] + bb.x;
        o.y = acc[i][1] + bb.y;
        o.z = acc[i][2] + bb.z;
        o.w = acc[i][3] + bb.w;
        *(float4*)&C[(row0 + ty * 4 + i) * 128 + tx * 4] = o;
    }
}

// ---------------- K3: edge writer (round-6 best) ----------------------------
// Edge e: recv = e/127, i = e%127, send = i + (i >= recv).
__global__ __launch_bounds__(512) void edge_out_kernel(float* __restrict__ out) {
    __shared__ float yr_sh[16 * 64];     // 4KB

    const int tid = threadIdx.x;
    const int b   = blockIdx.x >> 3;
    const int r0  = (blockIdx.x & 7) * 16;
    const int rowb = b << 7;

    if (tid < 256) {
        int node = tid >> 4, q = tid & 15;
        *(float4*)&yr_sh[node * 64 + q * 4] =
            *(const float4*)&g_y[(rowb + r0 + node) * 128 + 64 + q * 4];
    }

    const int q  = tid & 15;
    const int sg = tid >> 4;             // senders sg*4 .. +3
    float4 ys4[4];
    #pragma unroll
    for (int j = 0; j < 4; j++)
        ys4[j] = __ldg((const float4*)&g_y[(rowb + sg * 4 + j) * 128 + q * 4]);

    __syncthreads();

    float4* outv = (float4*)out;
    const long base_b = (long)b * NEDGE;

    #pragma unroll 1
    for (int rl = 0; rl < 16; rl++) {
        const int rg = r0 + rl;
        float4 yr4 = *(float4*)&yr_sh[rl * 64 + q * 4];
        const long base = (base_b + (long)rg * 127) * 16 + q;
        #pragma unroll
        for (int j = 0; j < 4; j++) {
            int s = sg * 4 + j;
            if (s == rg) continue;       // no self-loop
            int i = s - (s > rg);
            float4 o;
            o.x = ys4[j].x + yr4.x;
            o.y = ys4[j].y + yr4.y;
            o.z = ys4[j].z + yr4.z;
            o.w = ys4[j].w + yr4.w;
            __stcs(&outv[base + (long)i * 16], o);
        }
    }
}

// ---------------- launcher ---------------------------------------------------
extern "C" void kernel_launch(void* const* d_in, const int* in_sizes, int n_in,
                              void* d_out, int out_size) {
    const float* x       = (const float*)d_in[0];
    const float* W1      = (const float*)d_in[3];
    const float* b1      = (const float*)d_in[4];
    const float* W2      = (const float*)d_in[5];
    const float* b2      = (const float*)d_in[6];
    const float* gamma   = (const float*)d_in[7];
    const float* beta    = (const float*)d_in[8];
    const float* Wout    = (const float*)d_in[9];
    const float* bout    = (const float*)d_in[10];
    float* out = (float*)d_out;

    float *p_h2, *p_y, *p_psum, *p_psq;
    cudaGetSymbolAddress((void**)&p_h2,   g_h2);
    cudaGetSymbolAddress((void**)&p_y,    g_y);
    cudaGetSymbolAddress((void**)&p_psum, g_psum);
    cudaGetSymbolAddress((void**)&p_psq,  g_psq);

    static int attr_set = 0;
    if (!attr_set) {
        cudaFuncSetAttribute(mlp_fused_kernel,
                             cudaFuncAttributeMaxDynamicSharedMemorySize, 122880);
        cudaFuncSetAttribute(gemm3_kernel,
                             cudaFuncAttributeMaxDynamicSharedMemorySize, 81920);
        attr_set = 1;
    }

    // prep: weight transposes + counter reset (edge structure analytic)
    prep_kernel<<<40, 1024>>>(W1, W2, Wout);

    // fused MLP with resident weights (syncless k-loops) + last-block BN
    mlp_fused_kernel<<<NBLK, 256, 122880>>>(x, b1, b2, gamma, beta, Wout, bout,
                                            p_h2, p_psum, p_psq);

    // GEMM3 with resident sa-folded Wout
    gemm3_kernel<<<NBLK, 256, 81920>>>(p_h2, p_y);

    // edge output (write-floor bound)
    edge_out_kernel<<<256, 512>>>(out);
}